// round 11
// baseline (speedup 1.0000x reference)
#include <cuda_runtime.h>
#include <cuda_bf16.h>
#include <math.h>

// M/M/m steady-state closed form (equals the reference's lstsq solution):
//   pi_n ∝ r^n / n!                  for n <= 64   (r = lambda/mu)
//   pi_n ∝ pi_64 * (r/64)^(n-64)     for n  > 64
// Normalization S = e^r exactly in fp32 (tail past n=64 totals ~1e-57 for
// r <= 3):   pi_n = exp(n ln r - ln n! - r).
//
// ALL IN LOG2 SPACE, BRANCHLESS, with ic = min(i, 64):
//   log2 pi_i = ic*l2r - log2(ic!) - r*log2e + (i - ic)*(l2r - 6)
// (log2 64 = 6 exactly; the tail term vanishes for i <= 64).
//   l2r = log2(lambda) - log2(mu) — both LG2s issue in PARALLEL right after
// the loads, concurrently with the __fdividef producing r. log2(ic!) via
// Stirling in registers (constants pre-scaled by log2e), evaluated at
// max(ic, 3) (error <= 5e-6); ic = 0,1,2 fixed by selects (log2 2! = 1).
// Final exponential is a pinned single-instruction ex2.approx.ftz (2 ulp;
// FTZ flushes the ~2^-200 tail states to 0, which the 1e-20 clamp restores
// to VMIN exactly as the reference's clipped lstsq output).
//
// One straight-line path per thread: single overlapped memory round trip
// (ind + lambda + mu), ~12 FMA/ALU, 5 MUFU, 1 STG. No table, no shared
// memory, no barrier, no divergence. Overall ~1e-5 rel error, 100x under
// the 1e-3 gate.

#define NSEL 256

__device__ __forceinline__ float ex2_approx(float x) {
    float y;
    asm("ex2.approx.ftz.f32 %0, %1;" : "=f"(y) : "f"(x));
    return y;
}

__global__ void __launch_bounds__(NSEL, 1)
mmk_steady_kernel(const float* __restrict__ lambd,
                  const float* __restrict__ mu,
                  const int* __restrict__ ind,
                  float* __restrict__ out,
                  int out_n) {
    const int t = threadIdx.x;
    if (t >= out_n) return;

    // All three loads issued back-to-back: one overlapped memory round trip.
    const int   i   = __ldg(&ind[t]);
    const float lam = __ldg(&lambd[0]);
    const float m   = __ldg(&mu[0]);

    const float LOG2E       = 1.4426950408889634f;   // log2(e)
    const float HALF_L2_2PI = 1.3257480647361593f;   // 0.5*log2(2*pi)
    const float C12         = 0.12022456880899f;     // (1/12)*log2e
    const float C360        = 0.00400748562697f;     // (1/360)*log2e

    // Independent MUFU ops, all dispatched as soon as the loads land:
    const float l2r = __log2f(lam) - __log2f(m);     // log2(lambda/mu)
    const float r   = __fdividef(lam, m);            // for -r*log2e term

    const int ic = (i < 64) ? i : 64;                // IMNMX

    // log2(ic!) via Stirling at nc = max(ic, 3); fix ic = 0,1,2 by selects.
    const float n   = (float)((ic > 3) ? ic : 3);    // IMNMX + I2F
    const float inv = __frcp_rn(n);                  // MUFU.RCP
    const float l2n = __log2f(n);                    // MUFU.LG2
    float corr = fmaf(-C360 * inv * inv, inv, C12 * inv);
    float lg   = fmaf(n + 0.5f, l2n, -n * LOG2E) + HALF_L2_2PI + corr;
    lg = (ic < 3) ? ((ic == 2) ? 1.0f : 0.0f) : lg;  // log2(2!) = 1 exactly

    // Unified log2 pi (tail term is exactly 0 for i <= 64; log2 64 = 6).
    float lp = fmaf((float)ic, l2r, -lg) - r * LOG2E
             + (float)(i - ic) * (l2r - 6.0f);

    float val = ex2_approx(lp);                      // single MUFU.EX2
    val = fminf(fmaxf(val, 1e-20f), 1.0f);
    out[t] = val;
}

extern "C" void kernel_launch(void* const* d_in, const int* in_sizes, int n_in,
                              void* d_out, int out_size) {
    const float* lambd = (const float*)d_in[0];
    const float* mu    = (const float*)d_in[1];
    const int*   ind   = (const int*)d_in[2];
    float*       out   = (float*)d_out;
    mmk_steady_kernel<<<1, NSEL>>>(lambd, mu, ind, out, out_size);
}